// round 1
// baseline (speedup 1.0000x reference)
#include <cuda_runtime.h>

// Density-aware Chamfer loss, B=4, N=8192, 3D fp32.
// Pipeline:
//  1) zero_kernel: clear counts
//  2) nn_kernel:   brute-force argmin over ref slices (both directions in one grid)
//  3) reduce_kernel: merge per-slice partial argmins (first-min tie-break), histogram counts
//  4) finalize_kernel: exact gather distance + exp + density weight, deterministic block reduce

#define B_CONST   4
#define N_CONST   8192
#define S_SLICES  16
#define SLICE     (N_CONST / S_SLICES)   // 512
#define QPT       8
#define TPB       256
#define QPB       (TPB * QPT)            // 2048
#define QCHUNKS   (N_CONST / QPB)        // 4

// Scratch (static device arrays; no allocations allowed)
__device__ float g_pbest[2 * B_CONST * S_SLICES * N_CONST];
__device__ int   g_pidx [2 * B_CONST * S_SLICES * N_CONST];
__device__ int   g_idx  [2 * B_CONST * N_CONST];
__device__ int   g_cnt  [2 * B_CONST * N_CONST];

__global__ void zero_kernel() {
    int gid = blockIdx.x * blockDim.x + threadIdx.x;
    if (gid < 2 * B_CONST * N_CONST) g_cnt[gid] = 0;
}

// dir 0: queries = gts, refs = preds  (produces idx1 / dist1 side)
// dir 1: queries = preds, refs = gts  (produces idx2 / dist2 side)
__global__ __launch_bounds__(TPB) void nn_kernel(const float* __restrict__ gts,
                                                 const float* __restrict__ preds) {
    __shared__ float4 tile[SLICE];

    const int b   = blockIdx.z % B_CONST;
    const int dir = blockIdx.z / B_CONST;
    const int s   = blockIdx.y;
    const int qc  = blockIdx.x;

    const float* __restrict__ qptr = (dir == 0) ? gts : preds;
    const float* __restrict__ rptr = (dir == 0) ? preds : gts;

    // Load ref slice into shared as (x, y, z, |r|^2)
    const float* rbase = rptr + ((long)b * N_CONST + (long)s * SLICE) * 3;
    for (int i = threadIdx.x; i < SLICE; i += TPB) {
        float x = rbase[3 * i + 0];
        float y = rbase[3 * i + 1];
        float z = rbase[3 * i + 2];
        tile[i] = make_float4(x, y, z, x * x + y * y + z * z);
    }
    __syncthreads();

    // Load QPT queries per thread (strided for coalesced writes later)
    float qx[QPT], qy[QPT], qz[QPT], best[QPT];
    int   bidx[QPT];
    const int q0 = qc * QPB + threadIdx.x;
    const float* qbase = qptr + (long)b * N_CONST * 3;
    #pragma unroll
    for (int k = 0; k < QPT; k++) {
        int q = q0 + k * TPB;
        qx[k] = -2.0f * qbase[3 * q + 0];
        qy[k] = -2.0f * qbase[3 * q + 1];
        qz[k] = -2.0f * qbase[3 * q + 2];
        best[k] = 3.4e38f;
        bidx[k] = 0;
    }

    // Scan slice: d' = |r|^2 - 2 q.r (row-constant |q|^2 dropped; argmin-invariant)
    #pragma unroll 4
    for (int j = 0; j < SLICE; j++) {
        float4 r = tile[j];
        #pragma unroll
        for (int k = 0; k < QPT; k++) {
            float t = fmaf(qx[k], r.x, r.w);
            t = fmaf(qy[k], r.y, t);
            t = fmaf(qz[k], r.z, t);
            if (t < best[k]) { best[k] = t; bidx[k] = j; }  // strict <: first index wins
        }
    }

    const long base = ((long)(dir * B_CONST + b) * S_SLICES + s) * N_CONST;
    #pragma unroll
    for (int k = 0; k < QPT; k++) {
        int q = q0 + k * TPB;
        g_pbest[base + q] = best[k];
        g_pidx [base + q] = s * SLICE + bidx[k];
    }
}

__global__ void reduce_kernel() {
    int gid = blockIdx.x * blockDim.x + threadIdx.x;  // over 2*B*N queries
    if (gid >= 2 * B_CONST * N_CONST) return;
    const int db = gid / N_CONST;   // dir*B + b
    const int q  = gid % N_CONST;

    float best = 3.4e38f;
    int   bi   = 0;
    const long base = (long)db * S_SLICES * N_CONST + q;
    #pragma unroll
    for (int s = 0; s < S_SLICES; s++) {
        float v  = g_pbest[base + (long)s * N_CONST];
        int   id = g_pidx [base + (long)s * N_CONST];
        if (v < best) { best = v; bi = id; }   // ascending slice order => first-min tie-break
    }
    g_idx[gid] = bi;
    atomicAdd(&g_cnt[db * N_CONST + bi], 1);   // integer histogram: deterministic
}

__global__ void finalize_kernel(const float* __restrict__ gts,
                                const float* __restrict__ preds,
                                float* __restrict__ out) {
    __shared__ float ssum[256];
    const int b = blockIdx.x;
    float acc = 0.0f;

    #pragma unroll
    for (int dir = 0; dir < 2; dir++) {
        const float* __restrict__ qptr = (dir == 0) ? gts : preds;
        const float* __restrict__ rptr = (dir == 0) ? preds : gts;
        const int* __restrict__ idxp = g_idx + (dir * B_CONST + b) * N_CONST;
        const int* __restrict__ cntp = g_cnt + (dir * B_CONST + b) * N_CONST;
        const float* qb = qptr + (long)b * N_CONST * 3;
        const float* rb = rptr + (long)b * N_CONST * 3;

        for (int i = threadIdx.x; i < N_CONST; i += blockDim.x) {
            int id = idxp[i];
            // Exact gather distance like reference: sum((q - r[idx])^2)
            float dx = qb[3 * i + 0] - rb[3 * id + 0];
            float dy = qb[3 * i + 1] - rb[3 * id + 1];
            float dz = qb[3 * i + 2] - rb[3 * id + 2];
            float d  = dx * dx + dy * dy + dz * dz;
            float c  = (float)cntp[id];          // count^1.0 (N_LAMBDA = 1)
            // frac = 1 (n_x == n_gt); term = 1 - exp(-d*ALPHA) * 1/(c + EPS)
            acc += 1.0f - expf(-d) / (c + 1e-6f);
        }
    }

    ssum[threadIdx.x] = acc;
    __syncthreads();
    for (int off = 128; off > 0; off >>= 1) {
        if (threadIdx.x < off) ssum[threadIdx.x] += ssum[threadIdx.x + off];
        __syncthreads();
    }
    if (threadIdx.x == 0) out[b] = ssum[0] / (2.0f * (float)N_CONST);
}

extern "C" void kernel_launch(void* const* d_in, const int* in_sizes, int n_in,
                              void* d_out, int out_size) {
    const float* gts   = (const float*)d_in[0];
    const float* preds = (const float*)d_in[1];
    float* out = (float*)d_out;

    zero_kernel<<<(2 * B_CONST * N_CONST + 255) / 256, 256>>>();
    nn_kernel<<<dim3(QCHUNKS, S_SLICES, 2 * B_CONST), TPB>>>(gts, preds);
    reduce_kernel<<<(2 * B_CONST * N_CONST + 255) / 256, 256>>>();
    finalize_kernel<<<B_CONST, 256>>>(gts, preds, out);
}

// round 2
// speedup vs baseline: 1.4936x; 1.4936x over previous
#include <cuda_runtime.h>
#include <math_constants.h>

// Density-aware Chamfer loss, B=4, N=8192, 3D fp32.
//  zero_kernel      : clear counts
//  nn_kernel        : whole ref cloud in 128KB smem; packed fma.rn.f32x2 over
//                     j-pairs; group-min (32 refs) + winning-group rescan for
//                     exact first-argmin; histogram atomics inline
//  finalize_partial : 64-block gather/exp/weight partial sums
//  finalize_final   : fixed-order merge -> out[b]

#define B_CONST   4
#define N_CONST   8192
#define TPB       256
#define QPT       2
#define QPC       (TPB * QPT)          // 512 queries / CTA
#define QCHUNKS   (N_CONST / QPC)      // 16
#define GROUP     32                   // refs per group
#define JPG       (GROUP / 2)          // 16 j-pairs per group
#define NGROUPS   (N_CONST / GROUP)    // 256
#define SMEM_BYTES (N_CONST * 4 * sizeof(float))   // 131072

#define FIN_TPB   256
#define FIN_EPB   1024                 // entries per finalize block
#define FIN_BLOCKS (2 * B_CONST * N_CONST / FIN_EPB)  // 64

__device__ int   g_idx [2 * B_CONST * N_CONST];
__device__ int   g_cnt [2 * B_CONST * N_CONST];
__device__ float g_part[FIN_BLOCKS];

__global__ void zero_kernel() {
    int gid = blockIdx.x * blockDim.x + threadIdx.x;
    if (gid < 2 * B_CONST * N_CONST) g_cnt[gid] = 0;
}

// db = dir*B + b.  dir 0: queries = gts, refs = preds. dir 1: swapped.
__global__ __launch_bounds__(TPB, 1) void nn_kernel(const float* __restrict__ gts,
                                                    const float* __restrict__ preds) {
    extern __shared__ float s_tile[];   // interleaved: jj*8 -> rx0 rx1 ry0 ry1 rz0 rz1 rw0 rw1

    const int db  = blockIdx.y;
    const int b   = db & (B_CONST - 1);
    const int dir = db >> 2;
    const float* __restrict__ qptr = (dir == 0) ? gts : preds;
    const float* __restrict__ rptr = (dir == 0) ? preds : gts;

    // ---- load whole ref cloud into interleaved smem ----
    const float* rbase = rptr + (long)b * N_CONST * 3;
    for (int j = threadIdx.x; j < N_CONST; j += TPB) {
        float x = rbase[3 * j + 0];
        float y = rbase[3 * j + 1];
        float z = rbase[3 * j + 2];
        int jj = j >> 1, h = j & 1;
        float* p = s_tile + jj * 8;
        p[0 + h] = x;
        p[2 + h] = y;
        p[4 + h] = z;
        p[6 + h] = x * x + y * y + z * z;
    }
    __syncthreads();

    // ---- per-thread queries (scalar + packed-duplicated -2*q) ----
    const int q0 = blockIdx.x * QPC + threadIdx.x;
    const float* qbase = qptr + (long)b * N_CONST * 3;

    float qxs[QPT], qys[QPT], qzs[QPT];
    unsigned long long qx2[QPT], qy2[QPT], qz2[QPT];
    float best[QPT];
    int   gidw[QPT];
    float minE[QPT], minO[QPT];

    #pragma unroll
    for (int k = 0; k < QPT; k++) {
        int q = q0 + k * TPB;
        qxs[k] = -2.0f * qbase[3 * q + 0];
        qys[k] = -2.0f * qbase[3 * q + 1];
        qzs[k] = -2.0f * qbase[3 * q + 2];
        asm("mov.b64 %0, {%1, %1};" : "=l"(qx2[k]) : "f"(qxs[k]));
        asm("mov.b64 %0, {%1, %1};" : "=l"(qy2[k]) : "f"(qys[k]));
        asm("mov.b64 %0, {%1, %1};" : "=l"(qz2[k]) : "f"(qzs[k]));
        best[k] = CUDART_INF_F;
        gidw[k] = 0;
        minE[k] = CUDART_INF_F;
        minO[k] = CUDART_INF_F;
    }

    // ---- main scan: groups of 32 refs, packed over j-pairs ----
    for (int g = 0; g < NGROUPS; g++) {
        const float* gb = s_tile + g * JPG * 8;
        #pragma unroll
        for (int jj = 0; jj < JPG; jj++) {
            ulonglong2 A  = *(const ulonglong2*)(gb + jj * 8);      // {rx2, ry2}
            ulonglong2 Bv = *(const ulonglong2*)(gb + jj * 8 + 4);  // {rz2, rw2}
            #pragma unroll
            for (int k = 0; k < QPT; k++) {
                float tlo, thi;
                asm("{\n\t"
                    ".reg .b64 t;\n\t"
                    "fma.rn.f32x2 t, %2, %3, %4;\n\t"
                    "fma.rn.f32x2 t, %5, %6, t;\n\t"
                    "fma.rn.f32x2 t, %7, %8, t;\n\t"
                    "mov.b64 {%0, %1}, t;\n\t"
                    "}"
                    : "=f"(tlo), "=f"(thi)
                    : "l"(qx2[k]), "l"(A.x), "l"(Bv.y),
                      "l"(qy2[k]), "l"(A.y),
                      "l"(qz2[k]), "l"(Bv.x));
                minE[k] = fminf(minE[k], tlo);
                minO[k] = fminf(minO[k], thi);
            }
        }
        #pragma unroll
        for (int k = 0; k < QPT; k++) {
            float m = fminf(minE[k], minO[k]);
            if (m < best[k]) { best[k] = m; gidw[k] = g; }  // strict <: first group wins
            minE[k] = CUDART_INF_F;
            minO[k] = CUDART_INF_F;
        }
    }

    // ---- rescan winning group: exact bit-match recompute, first index wins ----
    #pragma unroll
    for (int k = 0; k < QPT; k++) {
        const int base = gidw[k] * GROUP;
        int idx = 0x7fffffff;
        #pragma unroll 8
        for (int j = 0; j < GROUP; j++) {
            int jj = (base + j) >> 1, h = (base + j) & 1;
            const float* p = s_tile + jj * 8;
            float t = fmaf(qxs[k], p[0 + h], p[6 + h]);
            t = fmaf(qys[k], p[2 + h], t);
            t = fmaf(qzs[k], p[4 + h], t);
            if (t == best[k]) idx = min(idx, base + j);
        }
        int q = q0 + k * TPB;
        g_idx[db * N_CONST + q] = idx;
        atomicAdd(&g_cnt[db * N_CONST + idx], 1);
    }
}

__global__ __launch_bounds__(FIN_TPB) void finalize_partial(const float* __restrict__ gts,
                                                            const float* __restrict__ preds) {
    __shared__ float ssum[FIN_TPB];
    float acc = 0.0f;
    const int e0 = blockIdx.x * FIN_EPB;

    #pragma unroll
    for (int i = 0; i < FIN_EPB / FIN_TPB; i++) {
        int e = e0 + i * FIN_TPB + threadIdx.x;   // global entry over (dir,b,q)
        int db = e / N_CONST;
        int q  = e - db * N_CONST;
        int b  = db & (B_CONST - 1);
        int dir = db >> 2;
        const float* qptr = (dir == 0) ? gts : preds;
        const float* rptr = (dir == 0) ? preds : gts;
        const float* qb = qptr + (long)b * N_CONST * 3;
        const float* rb = rptr + (long)b * N_CONST * 3;

        int id = g_idx[e];
        float dx = qb[3 * q + 0] - rb[3 * id + 0];
        float dy = qb[3 * q + 1] - rb[3 * id + 1];
        float dz = qb[3 * q + 2] - rb[3 * id + 2];
        float d  = dx * dx + dy * dy + dz * dz;
        float c  = (float)g_cnt[db * N_CONST + id];
        acc += 1.0f - expf(-d) / (c + 1e-6f);   // ALPHA=1, N_LAMBDA=1, frac=1
    }

    ssum[threadIdx.x] = acc;
    __syncthreads();
    for (int off = FIN_TPB / 2; off > 0; off >>= 1) {
        if (threadIdx.x < off) ssum[threadIdx.x] += ssum[threadIdx.x + off];
        __syncthreads();
    }
    if (threadIdx.x == 0) g_part[blockIdx.x] = ssum[0];
}

__global__ void finalize_final(float* __restrict__ out) {
    int b = threadIdx.x;
    if (b >= B_CONST) return;
    // blocks per db = N/FIN_EPB = 8; db = dir*B + b
    float s = 0.0f;
    #pragma unroll
    for (int dir = 0; dir < 2; dir++) {
        int db = dir * B_CONST + b;
        #pragma unroll
        for (int c = 0; c < N_CONST / FIN_EPB; c++)
            s += g_part[db * (N_CONST / FIN_EPB) + c];
    }
    out[b] = s / (2.0f * (float)N_CONST);
}

extern "C" void kernel_launch(void* const* d_in, const int* in_sizes, int n_in,
                              void* d_out, int out_size) {
    const float* gts   = (const float*)d_in[0];
    const float* preds = (const float*)d_in[1];
    float* out = (float*)d_out;

    cudaFuncSetAttribute(nn_kernel, cudaFuncAttributeMaxDynamicSharedMemorySize, SMEM_BYTES);

    zero_kernel<<<(2 * B_CONST * N_CONST + 255) / 256, 256>>>();
    nn_kernel<<<dim3(QCHUNKS, 2 * B_CONST), TPB, SMEM_BYTES>>>(gts, preds);
    finalize_partial<<<FIN_BLOCKS, FIN_TPB>>>(gts, preds);
    finalize_final<<<1, 32>>>(out);
}